// round 2
// baseline (speedup 1.0000x reference)
#include <cuda_runtime.h>
#include <cstdint>

// Problem constants
#define SEQ  2048
#define DIMD 2048
#define NHH  16
#define HDD  128
#define MROWS 4096   // B * SEQ

// ---------------------------------------------------------------------------
// Scratch (device globals; no allocation allowed)
// ---------------------------------------------------------------------------
__device__ float g_q[8388608];     // [MROWS][DIMD]
__device__ float g_k[8388608];
__device__ float g_v[8388608];
__device__ float g_attn[8388608];

// ---------------------------------------------------------------------------
// NT SGEMM: C[M,N] = A[M,K] * B[N,K]^T   (both K-major row-major)
// 128x128 block tile, BK=16, 8x8 per-thread microtile, 256 threads.
// Register-prefetch double buffering on the global->smem path.
// ---------------------------------------------------------------------------
#define BM 128
#define BN 128
#define BK 16

__global__ __launch_bounds__(256) void sgemm_nt(const float* __restrict__ A,
                                                const float* __restrict__ B,
                                                float* __restrict__ C,
                                                int Mdim, int Ndim, int Kdim) {
    __shared__ float As[BK][BM];
    __shared__ float Bs[BK][BN];
    const int tid = threadIdx.x;
    const int bm = blockIdx.y * BM;
    const int bn = blockIdx.x * BN;
    const int tx = tid & 15;
    const int ty = tid >> 4;

    // each thread owns 2 float4 loads of A and 2 of B per K-slab
    int f0 = tid;          // float4 id
    int f1 = tid + 256;
    int r0 = f0 >> 2, kq0 = (f0 & 3) << 2;
    int r1 = f1 >> 2, kq1 = (f1 & 3) << 2;

    const float* Ap0 = A + (size_t)(bm + r0) * Kdim + kq0;
    const float* Ap1 = A + (size_t)(bm + r1) * Kdim + kq1;
    const float* Bp0 = B + (size_t)(bn + r0) * Kdim + kq0;
    const float* Bp1 = B + (size_t)(bn + r1) * Kdim + kq1;

    float acc[8][8];
#pragma unroll
    for (int i = 0; i < 8; i++)
#pragma unroll
        for (int j = 0; j < 8; j++) acc[i][j] = 0.f;

    // prefetch slab 0
    float4 av0 = *(const float4*)(Ap0);
    float4 av1 = *(const float4*)(Ap1);
    float4 bv0 = *(const float4*)(Bp0);
    float4 bv1 = *(const float4*)(Bp1);

    for (int k0 = 0; k0 < Kdim; k0 += BK) {
        // store the prefetched slab
        As[kq0 + 0][r0] = av0.x; As[kq0 + 1][r0] = av0.y;
        As[kq0 + 2][r0] = av0.z; As[kq0 + 3][r0] = av0.w;
        As[kq1 + 0][r1] = av1.x; As[kq1 + 1][r1] = av1.y;
        As[kq1 + 2][r1] = av1.z; As[kq1 + 3][r1] = av1.w;
        Bs[kq0 + 0][r0] = bv0.x; Bs[kq0 + 1][r0] = bv0.y;
        Bs[kq0 + 2][r0] = bv0.z; Bs[kq0 + 3][r0] = bv0.w;
        Bs[kq1 + 0][r1] = bv1.x; Bs[kq1 + 1][r1] = bv1.y;
        Bs[kq1 + 2][r1] = bv1.z; Bs[kq1 + 3][r1] = bv1.w;
        __syncthreads();

        // prefetch slab k0+BK while computing on current slab
        if (k0 + BK < Kdim) {
            av0 = *(const float4*)(Ap0 + k0 + BK);
            av1 = *(const float4*)(Ap1 + k0 + BK);
            bv0 = *(const float4*)(Bp0 + k0 + BK);
            bv1 = *(const float4*)(Bp1 + k0 + BK);
        }

#pragma unroll
        for (int kk = 0; kk < BK; kk++) {
            float a[8], b[8];
            *(float4*)(a)     = *(const float4*)(&As[kk][ty * 8]);
            *(float4*)(a + 4) = *(const float4*)(&As[kk][ty * 8 + 4]);
            *(float4*)(b)     = *(const float4*)(&Bs[kk][tx * 8]);
            *(float4*)(b + 4) = *(const float4*)(&Bs[kk][tx * 8 + 4]);
#pragma unroll
            for (int i = 0; i < 8; i++)
#pragma unroll
                for (int j = 0; j < 8; j++) acc[i][j] += a[i] * b[j];
        }
        __syncthreads();
    }
#pragma unroll
    for (int i = 0; i < 8; i++) {
        size_t row = (size_t)(bm + ty * 8 + i);
        float* cp = C + row * Ndim + bn + tx * 8;
        *(float4*)(cp)     = make_float4(acc[i][0], acc[i][1], acc[i][2], acc[i][3]);
        *(float4*)(cp + 4) = make_float4(acc[i][4], acc[i][5], acc[i][6], acc[i][7]);
    }
}

// ---------------------------------------------------------------------------
// RoPE (in-place on q and k). Pairs (2i, 2i+1) within each head.
// freqs_cis layout: [SEQ][HD/2][2] = cos, sin
// ---------------------------------------------------------------------------
__global__ void rope_kernel(float* __restrict__ q, float* __restrict__ k,
                            const float* __restrict__ fc) {
    int idx = blockIdx.x * blockDim.x + threadIdx.x;   // pair index
    if (idx >= MROWS * (DIMD / 2)) return;
    int row = idx >> 10;        // / (DIMD/2)
    int p   = idx & 1023;       // pair within row
    int i   = p & 63;           // pair within head (HD/2 = 64)
    int s   = row & (SEQ - 1);  // sequence position
    float c  = fc[(s * 64 + i) * 2 + 0];
    float sn = fc[(s * 64 + i) * 2 + 1];
    float2* qp = (float2*)q + idx;
    float2* kp = (float2*)k + idx;
    float2 qv = *qp, kv = *kp;
    *qp = make_float2(qv.x * c - qv.y * sn, qv.x * sn + qv.y * c);
    *kp = make_float2(kv.x * c - kv.y * sn, kv.x * sn + kv.y * c);
}

// ---------------------------------------------------------------------------
// Causal flash attention, fp32, Q-tile 64, K-tile 64.
// Block = (q_tile, head, batch), 256 threads: 16x16 grid, 4 rows x 4 cols of
// scores per thread, 4 rows x 8 d-cols of O accumulator.
// K tile stored with a float4-granular XOR swizzle for conflict-free reads.
// ---------------------------------------------------------------------------
__global__ __launch_bounds__(256) void flash_kernel(const float* __restrict__ Q,
                                                    const float* __restrict__ K,
                                                    const float* __restrict__ V,
                                                    float* __restrict__ O) {
    extern __shared__ float sm[];
    float* Qs = sm;                     // [64][128]
    float* Ks = Qs + 64 * 128;          // [64][128] swizzled
    float* Vs = Ks + 64 * 128;          // [64][128]
    float* Ps = Vs + 64 * 128;          // [64][65]
    const int qt = (int)gridDim.x - 1 - (int)blockIdx.x;   // heavy tiles first
    const int h  = blockIdx.y;
    const int b  = blockIdx.z;
    const int tid = threadIdx.x;
    const int tx = tid & 15;
    const int ty = tid >> 4;
    const int q0 = qt * 64;
    const size_t base = (size_t)b * SEQ * DIMD + (size_t)h * HDD;
    const float* qg = Q + base;
    const float* kg = K + base;
    const float* vg = V + base;

    for (int t = tid; t < 64 * 32; t += 256) {
        int r = t >> 5, d4 = t & 31;
        ((float4*)(Qs + r * 128))[d4] =
            ((const float4*)(qg + (size_t)(q0 + r) * DIMD))[d4];
    }
    float m_i[4], l_i[4], oac[4][8];
#pragma unroll
    for (int i = 0; i < 4; i++) {
        m_i[i] = -1e30f; l_i[i] = 0.f;
#pragma unroll
        for (int j = 0; j < 8; j++) oac[i][j] = 0.f;
    }
    __syncthreads();
    const float scale = 0.08838834764831845f;   // 1/sqrt(128)

    for (int kt = 0; kt <= qt; kt++) {
        const int k0 = kt * 64;
        for (int t = tid; t < 64 * 32; t += 256) {
            int c = t >> 5, d4 = t & 31;
            ((float4*)(Ks + c * 128))[d4 ^ (c & 7)] =
                ((const float4*)(kg + (size_t)(k0 + c) * DIMD))[d4];
            ((float4*)(Vs + c * 128))[d4] =
                ((const float4*)(vg + (size_t)(k0 + c) * DIMD))[d4];
        }
        __syncthreads();

        // scores: rows ty*4+i, cols tx + 16*j
        float sc[4][4];
#pragma unroll
        for (int i = 0; i < 4; i++)
#pragma unroll
            for (int j = 0; j < 4; j++) sc[i][j] = 0.f;

#pragma unroll 8
        for (int d4 = 0; d4 < 32; d4++) {
            float4 qv[4];
#pragma unroll
            for (int i = 0; i < 4; i++)
                qv[i] = ((const float4*)(Qs + (ty * 4 + i) * 128))[d4];
#pragma unroll
            for (int j = 0; j < 4; j++) {
                int c = tx + 16 * j;
                float4 kv = ((const float4*)(Ks + c * 128))[d4 ^ (c & 7)];
#pragma unroll
                for (int i = 0; i < 4; i++)
                    sc[i][j] += qv[i].x * kv.x + qv[i].y * kv.y +
                                qv[i].z * kv.z + qv[i].w * kv.w;
            }
        }

        // scale + causal mask (diagonal tile only)
        const bool diag = (kt == qt);
#pragma unroll
        for (int i = 0; i < 4; i++) {
            int qrow = q0 + ty * 4 + i;
#pragma unroll
            for (int j = 0; j < 4; j++) {
                float v = sc[i][j] * scale;
                if (diag && (k0 + tx + 16 * j) > qrow) v = -1e30f;
                sc[i][j] = v;
            }
        }

        // online softmax; row owned by 16 lanes sharing ty (lanes 0-15 / 16-31)
#pragma unroll
        for (int i = 0; i < 4; i++) {
            float rmax = fmaxf(fmaxf(sc[i][0], sc[i][1]),
                               fmaxf(sc[i][2], sc[i][3]));
#pragma unroll
            for (int off = 8; off >= 1; off >>= 1)
                rmax = fmaxf(rmax, __shfl_xor_sync(0xffffffffu, rmax, off));
            float mnew = fmaxf(m_i[i], rmax);
            float corr = __expf(m_i[i] - mnew);
            m_i[i] = mnew;
            l_i[i] *= corr;
#pragma unroll
            for (int jj = 0; jj < 8; jj++) oac[i][jj] *= corr;
            float rs = 0.f;
#pragma unroll
            for (int j = 0; j < 4; j++) {
                float p = __expf(sc[i][j] - mnew);
                sc[i][j] = p;
                rs += p;
            }
#pragma unroll
            for (int off = 8; off >= 1; off >>= 1)
                rs += __shfl_xor_sync(0xffffffffu, rs, off);
            l_i[i] += rs;
#pragma unroll
            for (int j = 0; j < 4; j++)
                Ps[(ty * 4 + i) * 65 + tx + 16 * j] = sc[i][j];
        }
        __syncthreads();

        // O += P * V   (thread: rows ty*4+i, d-cols tx*8 .. tx*8+7)
#pragma unroll 4
        for (int c = 0; c < 64; c++) {
            float4 v0 = ((const float4*)(Vs + c * 128))[tx * 2];
            float4 v1 = ((const float4*)(Vs + c * 128))[tx * 2 + 1];
#pragma unroll
            for (int i = 0; i < 4; i++) {
                float p = Ps[(ty * 4 + i) * 65 + c];
                oac[i][0] += p * v0.x; oac[i][1] += p * v0.y;
                oac[i][2] += p * v0.z; oac[i][3] += p * v0.w;
                oac[i][4] += p * v1.x; oac[i][5] += p * v1.y;
                oac[i][6] += p * v1.z; oac[i][7] += p * v1.w;
            }
        }
        __syncthreads();
    }

    // normalize and write O
#pragma unroll
    for (int i = 0; i < 4; i++) {
        float inv = 1.f / l_i[i];
        size_t row = (size_t)(q0 + ty * 4 + i);
        float* op = O + base + row * DIMD + tx * 8;
        *(float4*)op = make_float4(oac[i][0] * inv, oac[i][1] * inv,
                                   oac[i][2] * inv, oac[i][3] * inv);
        *(float4*)(op + 4) = make_float4(oac[i][4] * inv, oac[i][5] * inv,
                                         oac[i][6] * inv, oac[i][7] * inv);
    }
}

// ---------------------------------------------------------------------------
// launcher
// ---------------------------------------------------------------------------
extern "C" void kernel_launch(void* const* d_in, const int* in_sizes, int n_in,
                              void* d_out, int out_size) {
    // metadata order: x, start_pos, freqs_cis, mask, wq, wk, wv, wo
    const float* x  = (const float*)d_in[0];
    const float* fc = (const float*)d_in[2];
    const float* wq = (const float*)d_in[4];
    const float* wk = (const float*)d_in[5];
    const float* wv = (const float*)d_in[6];
    const float* wo = (const float*)d_in[7];
    float* out = (float*)d_out;

    float *q, *k, *v, *attn;
    cudaGetSymbolAddress((void**)&q, g_q);
    cudaGetSymbolAddress((void**)&k, g_k);
    cudaGetSymbolAddress((void**)&v, g_v);
    cudaGetSymbolAddress((void**)&attn, g_attn);

    const size_t FLASH_SMEM = (size_t)(64 * 128 * 3 + 64 * 65) * sizeof(float);
    cudaFuncSetAttribute(flash_kernel,
                         cudaFuncAttributeMaxDynamicSharedMemorySize,
                         (int)FLASH_SMEM);

    dim3 ggrid(DIMD / BN, MROWS / BM);
    sgemm_nt<<<ggrid, 256>>>(x, wq, q, MROWS, DIMD, DIMD);
    sgemm_nt<<<ggrid, 256>>>(x, wk, k, MROWS, DIMD, DIMD);
    sgemm_nt<<<ggrid, 256>>>(x, wv, v, MROWS, DIMD, DIMD);

    rope_kernel<<<(MROWS * (DIMD / 2) + 255) / 256, 256>>>(q, k, fc);

    flash_kernel<<<dim3(SEQ / 64, NHH, 2), 256, FLASH_SMEM>>>(q, k, v, attn);

    sgemm_nt<<<ggrid, 256>>>(attn, wo, out, MROWS, DIMD, DIMD);
}

// round 3
// speedup vs baseline: 2.1239x; 2.1239x over previous
#include <cuda_runtime.h>
#include <cstdint>

// Problem constants
#define SEQ  2048
#define DIMD 2048
#define NHH  16
#define HDD  128
#define MROWS 4096   // B * SEQ

// ---------------------------------------------------------------------------
// Scratch (device globals; no allocation allowed)
// ---------------------------------------------------------------------------
__device__ float g_q[8388608];     // [MROWS][DIMD]
__device__ float g_k[8388608];
__device__ float g_v[8388608];
__device__ float g_attn[8388608];

// ---------------------------------------------------------------------------
// tf32 NT GEMM via mma.sync.m16n8k8:
//   C[M,N] = A[M,K] * B[N,K]^T   (both row-major, K contiguous)
// Block tile 128x128x32, 256 threads = 8 warps (2 x 4), warp tile 64x32.
// smem padded [row][36] => fragment scalar LDS is conflict-free.
// cvt.rna.tf32.f32 applied at smem store; register-prefetch double buffering.
// ---------------------------------------------------------------------------
__device__ __forceinline__ float to_tf32(float x) {
    float y;
    asm("cvt.rna.tf32.f32 %0, %1;" : "=f"(y) : "f"(x));
    return y;
}

__global__ __launch_bounds__(256) void tf32_gemm_nt(const float* __restrict__ A,
                                                    const float* __restrict__ B,
                                                    float* __restrict__ C,
                                                    int Kdim, int Ndim) {
    __shared__ float As[128][36];
    __shared__ float Bs[128][36];

    const int tid = threadIdx.x;
    const int bm = blockIdx.y * 128;
    const int bn = blockIdx.x * 128;
    const int wid  = tid >> 5;
    const int lane = tid & 31;
    const int wm = (wid >> 2) * 64;    // warp M offset within block (0/64)
    const int wn = (wid & 3) * 32;     // warp N offset within block (0..96)
    const int g  = lane >> 2;          // group id 0..7
    const int t  = lane & 3;           // thread-in-group 0..3

    // gmem load assignment: 1024 float4 per matrix per slab; 4 per thread.
    const int row0 = tid >> 3;          // 0..31 (+32 per 'it')
    const int kq4  = (tid & 7) << 2;    // float4 k offset 0..28
    const float* Ab = A + (size_t)(bm + row0) * Kdim + kq4;
    const float* Bb = B + (size_t)(bn + row0) * Kdim + kq4;

    float acc[4][4][4];
#pragma unroll
    for (int mi = 0; mi < 4; mi++)
#pragma unroll
        for (int ni = 0; ni < 4; ni++)
#pragma unroll
            for (int c = 0; c < 4; c++) acc[mi][ni][c] = 0.f;

    float4 av[4], bv[4];
    // prefetch slab 0
#pragma unroll
    for (int it = 0; it < 4; it++) {
        av[it] = *(const float4*)(Ab + (size_t)it * 32 * Kdim);
        bv[it] = *(const float4*)(Bb + (size_t)it * 32 * Kdim);
    }

    for (int k0 = 0; k0 < Kdim; k0 += 32) {
        // store prefetched slab (tf32-rounded)
#pragma unroll
        for (int it = 0; it < 4; it++) {
            int r = row0 + it * 32;
            As[r][kq4 + 0] = to_tf32(av[it].x);
            As[r][kq4 + 1] = to_tf32(av[it].y);
            As[r][kq4 + 2] = to_tf32(av[it].z);
            As[r][kq4 + 3] = to_tf32(av[it].w);
            Bs[r][kq4 + 0] = to_tf32(bv[it].x);
            Bs[r][kq4 + 1] = to_tf32(bv[it].y);
            Bs[r][kq4 + 2] = to_tf32(bv[it].z);
            Bs[r][kq4 + 3] = to_tf32(bv[it].w);
        }
        __syncthreads();

        // prefetch next slab while computing
        if (k0 + 32 < Kdim) {
#pragma unroll
            for (int it = 0; it < 4; it++) {
                av[it] = *(const float4*)(Ab + (size_t)it * 32 * Kdim + k0 + 32);
                bv[it] = *(const float4*)(Bb + (size_t)it * 32 * Kdim + k0 + 32);
            }
        }

#pragma unroll
        for (int ks = 0; ks < 4; ks++) {
            const int kk = ks * 8;
            uint32_t ua[4][4], ub[4][2];
#pragma unroll
            for (int mi = 0; mi < 4; mi++) {
                const int m0 = wm + mi * 16;
                ua[mi][0] = __float_as_uint(As[m0 + g][kk + t]);
                ua[mi][1] = __float_as_uint(As[m0 + g + 8][kk + t]);
                ua[mi][2] = __float_as_uint(As[m0 + g][kk + t + 4]);
                ua[mi][3] = __float_as_uint(As[m0 + g + 8][kk + t + 4]);
            }
#pragma unroll
            for (int ni = 0; ni < 4; ni++) {
                const int n0 = wn + ni * 8;
                ub[ni][0] = __float_as_uint(Bs[n0 + g][kk + t]);
                ub[ni][1] = __float_as_uint(Bs[n0 + g][kk + t + 4]);
            }
#pragma unroll
            for (int mi = 0; mi < 4; mi++)
#pragma unroll
                for (int ni = 0; ni < 4; ni++) {
                    asm volatile(
                        "mma.sync.aligned.m16n8k8.row.col.f32.tf32.tf32.f32 "
                        "{%0,%1,%2,%3}, {%4,%5,%6,%7}, {%8,%9}, {%0,%1,%2,%3};"
                        : "+f"(acc[mi][ni][0]), "+f"(acc[mi][ni][1]),
                          "+f"(acc[mi][ni][2]), "+f"(acc[mi][ni][3])
                        : "r"(ua[mi][0]), "r"(ua[mi][1]),
                          "r"(ua[mi][2]), "r"(ua[mi][3]),
                          "r"(ub[ni][0]), "r"(ub[ni][1]));
                }
        }
        __syncthreads();
    }

    // epilogue: c0,c1 -> row g, cols 2t,2t+1 ; c2,c3 -> row g+8
#pragma unroll
    for (int mi = 0; mi < 4; mi++) {
#pragma unroll
        for (int ni = 0; ni < 4; ni++) {
            const size_t r0 = (size_t)(bm + wm + mi * 16 + g);
            const int   c0 = bn + wn + ni * 8 + 2 * t;
            *(float2*)(C + r0 * Ndim + c0) =
                make_float2(acc[mi][ni][0], acc[mi][ni][1]);
            *(float2*)(C + (r0 + 8) * Ndim + c0) =
                make_float2(acc[mi][ni][2], acc[mi][ni][3]);
        }
    }
}

// ---------------------------------------------------------------------------
// RoPE (in-place on q and k). Pairs (2i, 2i+1) within each head.
// freqs_cis layout: [SEQ][HD/2][2] = cos, sin
// ---------------------------------------------------------------------------
__global__ void rope_kernel(float* __restrict__ q, float* __restrict__ k,
                            const float* __restrict__ fc) {
    int idx = blockIdx.x * blockDim.x + threadIdx.x;   // pair index
    if (idx >= MROWS * (DIMD / 2)) return;
    int row = idx >> 10;        // / (DIMD/2)
    int p   = idx & 1023;       // pair within row
    int i   = p & 63;           // pair within head (HD/2 = 64)
    int s   = row & (SEQ - 1);  // sequence position
    float c  = fc[(s * 64 + i) * 2 + 0];
    float sn = fc[(s * 64 + i) * 2 + 1];
    float2* qp = (float2*)q + idx;
    float2* kp = (float2*)k + idx;
    float2 qv = *qp, kv = *kp;
    *qp = make_float2(qv.x * c - qv.y * sn, qv.x * sn + qv.y * c);
    *kp = make_float2(kv.x * c - kv.y * sn, kv.x * sn + kv.y * c);
}

// ---------------------------------------------------------------------------
// Causal flash attention, fp32, Q-tile 64, K-tile 64. (unchanged from R2)
// ---------------------------------------------------------------------------
__global__ __launch_bounds__(256) void flash_kernel(const float* __restrict__ Q,
                                                    const float* __restrict__ K,
                                                    const float* __restrict__ V,
                                                    float* __restrict__ O) {
    extern __shared__ float sm[];
    float* Qs = sm;                     // [64][128]
    float* Ks = Qs + 64 * 128;          // [64][128] swizzled
    float* Vs = Ks + 64 * 128;          // [64][128]
    float* Ps = Vs + 64 * 128;          // [64][65]
    const int qt = (int)gridDim.x - 1 - (int)blockIdx.x;   // heavy tiles first
    const int h  = blockIdx.y;
    const int b  = blockIdx.z;
    const int tid = threadIdx.x;
    const int tx = tid & 15;
    const int ty = tid >> 4;
    const int q0 = qt * 64;
    const size_t base = (size_t)b * SEQ * DIMD + (size_t)h * HDD;
    const float* qg = Q + base;
    const float* kg = K + base;
    const float* vg = V + base;

    for (int t = tid; t < 64 * 32; t += 256) {
        int r = t >> 5, d4 = t & 31;
        ((float4*)(Qs + r * 128))[d4] =
            ((const float4*)(qg + (size_t)(q0 + r) * DIMD))[d4];
    }
    float m_i[4], l_i[4], oac[4][8];
#pragma unroll
    for (int i = 0; i < 4; i++) {
        m_i[i] = -1e30f; l_i[i] = 0.f;
#pragma unroll
        for (int j = 0; j < 8; j++) oac[i][j] = 0.f;
    }
    __syncthreads();
    const float scale = 0.08838834764831845f;   // 1/sqrt(128)

    for (int kt = 0; kt <= qt; kt++) {
        const int k0 = kt * 64;
        for (int t = tid; t < 64 * 32; t += 256) {
            int c = t >> 5, d4 = t & 31;
            ((float4*)(Ks + c * 128))[d4 ^ (c & 7)] =
                ((const float4*)(kg + (size_t)(k0 + c) * DIMD))[d4];
            ((float4*)(Vs + c * 128))[d4] =
                ((const float4*)(vg + (size_t)(k0 + c) * DIMD))[d4];
        }
        __syncthreads();

        float sc[4][4];
#pragma unroll
        for (int i = 0; i < 4; i++)
#pragma unroll
            for (int j = 0; j < 4; j++) sc[i][j] = 0.f;

#pragma unroll 8
        for (int d4 = 0; d4 < 32; d4++) {
            float4 qv[4];
#pragma unroll
            for (int i = 0; i < 4; i++)
                qv[i] = ((const float4*)(Qs + (ty * 4 + i) * 128))[d4];
#pragma unroll
            for (int j = 0; j < 4; j++) {
                int c = tx + 16 * j;
                float4 kv = ((const float4*)(Ks + c * 128))[d4 ^ (c & 7)];
#pragma unroll
                for (int i = 0; i < 4; i++)
                    sc[i][j] += qv[i].x * kv.x + qv[i].y * kv.y +
                                qv[i].z * kv.z + qv[i].w * kv.w;
            }
        }

        const bool diag = (kt == qt);
#pragma unroll
        for (int i = 0; i < 4; i++) {
            int qrow = q0 + ty * 4 + i;
#pragma unroll
            for (int j = 0; j < 4; j++) {
                float v = sc[i][j] * scale;
                if (diag && (k0 + tx + 16 * j) > qrow) v = -1e30f;
                sc[i][j] = v;
            }
        }

#pragma unroll
        for (int i = 0; i < 4; i++) {
            float rmax = fmaxf(fmaxf(sc[i][0], sc[i][1]),
                               fmaxf(sc[i][2], sc[i][3]));
#pragma unroll
            for (int off = 8; off >= 1; off >>= 1)
                rmax = fmaxf(rmax, __shfl_xor_sync(0xffffffffu, rmax, off));
            float mnew = fmaxf(m_i[i], rmax);
            float corr = __expf(m_i[i] - mnew);
            m_i[i] = mnew;
            l_i[i] *= corr;
#pragma unroll
            for (int jj = 0; jj < 8; jj++) oac[i][jj] *= corr;
            float rs = 0.f;
#pragma unroll
            for (int j = 0; j < 4; j++) {
                float p = __expf(sc[i][j] - mnew);
                sc[i][j] = p;
                rs += p;
            }
#pragma unroll
            for (int off = 8; off >= 1; off >>= 1)
                rs += __shfl_xor_sync(0xffffffffu, rs, off);
            l_i[i] += rs;
#pragma unroll
            for (int j = 0; j < 4; j++)
                Ps[(ty * 4 + i) * 65 + tx + 16 * j] = sc[i][j];
        }
        __syncthreads();

#pragma unroll 4
        for (int c = 0; c < 64; c++) {
            float4 v0 = ((const float4*)(Vs + c * 128))[tx * 2];
            float4 v1 = ((const float4*)(Vs + c * 128))[tx * 2 + 1];
#pragma unroll
            for (int i = 0; i < 4; i++) {
                float p = Ps[(ty * 4 + i) * 65 + c];
                oac[i][0] += p * v0.x; oac[i][1] += p * v0.y;
                oac[i][2] += p * v0.z; oac[i][3] += p * v0.w;
                oac[i][4] += p * v1.x; oac[i][5] += p * v1.y;
                oac[i][6] += p * v1.z; oac[i][7] += p * v1.w;
            }
        }
        __syncthreads();
    }

#pragma unroll
    for (int i = 0; i < 4; i++) {
        float inv = 1.f / l_i[i];
        size_t row = (size_t)(q0 + ty * 4 + i);
        float* op = O + base + row * DIMD + tx * 8;
        *(float4*)op = make_float4(oac[i][0] * inv, oac[i][1] * inv,
                                   oac[i][2] * inv, oac[i][3] * inv);
        *(float4*)(op + 4) = make_float4(oac[i][4] * inv, oac[i][5] * inv,
                                         oac[i][6] * inv, oac[i][7] * inv);
    }
}

// ---------------------------------------------------------------------------
// launcher
// ---------------------------------------------------------------------------
extern "C" void kernel_launch(void* const* d_in, const int* in_sizes, int n_in,
                              void* d_out, int out_size) {
    // metadata order: x, start_pos, freqs_cis, mask, wq, wk, wv, wo
    const float* x  = (const float*)d_in[0];
    const float* fc = (const float*)d_in[2];
    const float* wq = (const float*)d_in[4];
    const float* wk = (const float*)d_in[5];
    const float* wv = (const float*)d_in[6];
    const float* wo = (const float*)d_in[7];
    float* out = (float*)d_out;

    float *q, *k, *v, *attn;
    cudaGetSymbolAddress((void**)&q, g_q);
    cudaGetSymbolAddress((void**)&k, g_k);
    cudaGetSymbolAddress((void**)&v, g_v);
    cudaGetSymbolAddress((void**)&attn, g_attn);

    const size_t FLASH_SMEM = (size_t)(64 * 128 * 3 + 64 * 65) * sizeof(float);
    cudaFuncSetAttribute(flash_kernel,
                         cudaFuncAttributeMaxDynamicSharedMemorySize,
                         (int)FLASH_SMEM);

    dim3 ggrid(DIMD / 128, MROWS / 128);
    tf32_gemm_nt<<<ggrid, 256>>>(x, wq, q, DIMD, DIMD);
    tf32_gemm_nt<<<ggrid, 256>>>(x, wk, k, DIMD, DIMD);
    tf32_gemm_nt<<<ggrid, 256>>>(x, wv, v, DIMD, DIMD);

    rope_kernel<<<(MROWS * (DIMD / 2) + 255) / 256, 256>>>(q, k, fc);

    flash_kernel<<<dim3(SEQ / 64, NHH, 2), 256, FLASH_SMEM>>>(q, k, v, attn);

    tf32_gemm_nt<<<ggrid, 256>>>(attn, wo, out, DIMD, DIMD);
}

// round 4
// speedup vs baseline: 3.2907x; 1.5493x over previous
#include <cuda_runtime.h>
#include <cstdint>

// Problem constants
#define SEQ  2048
#define DIMD 2048
#define NHH  16
#define HDD  128
#define MROWS 4096   // B * SEQ

// ---------------------------------------------------------------------------
// Scratch (device globals; no allocation allowed)
// ---------------------------------------------------------------------------
__device__ float g_q[8388608];     // [MROWS][DIMD]
__device__ float g_k[8388608];
__device__ float g_v[8388608];
__device__ float g_attn[8388608];

__device__ __forceinline__ float to_tf32(float x) {
    float y;
    asm("cvt.rna.tf32.f32 %0, %1;" : "=f"(y) : "f"(x));
    return y;
}

#define MMA_TF32(acc, a0, a1, a2, a3, b0, b1)                                 \
    asm volatile(                                                             \
        "mma.sync.aligned.m16n8k8.row.col.f32.tf32.tf32.f32 "                 \
        "{%0,%1,%2,%3}, {%4,%5,%6,%7}, {%8,%9}, {%0,%1,%2,%3};"               \
        : "+f"((acc)[0]), "+f"((acc)[1]), "+f"((acc)[2]), "+f"((acc)[3])      \
        : "r"(a0), "r"(a1), "r"(a2), "r"(a3), "r"(b0), "r"(b1))

// ---------------------------------------------------------------------------
// tf32 NT GEMM via mma.sync.m16n8k8 (unchanged from R3):
//   C[M,N] = A[M,K] * B[N,K]^T
// ---------------------------------------------------------------------------
__global__ __launch_bounds__(256) void tf32_gemm_nt(const float* __restrict__ A,
                                                    const float* __restrict__ B,
                                                    float* __restrict__ C,
                                                    int Kdim, int Ndim) {
    __shared__ float As[128][36];
    __shared__ float Bs[128][36];

    const int tid = threadIdx.x;
    const int bm = blockIdx.y * 128;
    const int bn = blockIdx.x * 128;
    const int wid  = tid >> 5;
    const int lane = tid & 31;
    const int wm = (wid >> 2) * 64;
    const int wn = (wid & 3) * 32;
    const int g  = lane >> 2;
    const int t  = lane & 3;

    const int row0 = tid >> 3;
    const int kq4  = (tid & 7) << 2;
    const float* Ab = A + (size_t)(bm + row0) * Kdim + kq4;
    const float* Bb = B + (size_t)(bn + row0) * Kdim + kq4;

    float acc[4][4][4];
#pragma unroll
    for (int mi = 0; mi < 4; mi++)
#pragma unroll
        for (int ni = 0; ni < 4; ni++)
#pragma unroll
            for (int c = 0; c < 4; c++) acc[mi][ni][c] = 0.f;

    float4 av[4], bv[4];
#pragma unroll
    for (int it = 0; it < 4; it++) {
        av[it] = *(const float4*)(Ab + (size_t)it * 32 * Kdim);
        bv[it] = *(const float4*)(Bb + (size_t)it * 32 * Kdim);
    }

    for (int k0 = 0; k0 < Kdim; k0 += 32) {
#pragma unroll
        for (int it = 0; it < 4; it++) {
            int r = row0 + it * 32;
            As[r][kq4 + 0] = to_tf32(av[it].x);
            As[r][kq4 + 1] = to_tf32(av[it].y);
            As[r][kq4 + 2] = to_tf32(av[it].z);
            As[r][kq4 + 3] = to_tf32(av[it].w);
            Bs[r][kq4 + 0] = to_tf32(bv[it].x);
            Bs[r][kq4 + 1] = to_tf32(bv[it].y);
            Bs[r][kq4 + 2] = to_tf32(bv[it].z);
            Bs[r][kq4 + 3] = to_tf32(bv[it].w);
        }
        __syncthreads();

        if (k0 + 32 < Kdim) {
#pragma unroll
            for (int it = 0; it < 4; it++) {
                av[it] = *(const float4*)(Ab + (size_t)it * 32 * Kdim + k0 + 32);
                bv[it] = *(const float4*)(Bb + (size_t)it * 32 * Kdim + k0 + 32);
            }
        }

#pragma unroll
        for (int ks = 0; ks < 4; ks++) {
            const int kk = ks * 8;
            uint32_t ua[4][4], ub[4][2];
#pragma unroll
            for (int mi = 0; mi < 4; mi++) {
                const int m0 = wm + mi * 16;
                ua[mi][0] = __float_as_uint(As[m0 + g][kk + t]);
                ua[mi][1] = __float_as_uint(As[m0 + g + 8][kk + t]);
                ua[mi][2] = __float_as_uint(As[m0 + g][kk + t + 4]);
                ua[mi][3] = __float_as_uint(As[m0 + g + 8][kk + t + 4]);
            }
#pragma unroll
            for (int ni = 0; ni < 4; ni++) {
                const int n0 = wn + ni * 8;
                ub[ni][0] = __float_as_uint(Bs[n0 + g][kk + t]);
                ub[ni][1] = __float_as_uint(Bs[n0 + g][kk + t + 4]);
            }
#pragma unroll
            for (int mi = 0; mi < 4; mi++)
#pragma unroll
                for (int ni = 0; ni < 4; ni++)
                    MMA_TF32(acc[mi][ni], ua[mi][0], ua[mi][1], ua[mi][2],
                             ua[mi][3], ub[ni][0], ub[ni][1]);
        }
        __syncthreads();
    }

#pragma unroll
    for (int mi = 0; mi < 4; mi++) {
#pragma unroll
        for (int ni = 0; ni < 4; ni++) {
            const size_t r0 = (size_t)(bm + wm + mi * 16 + g);
            const int   c0 = bn + wn + ni * 8 + 2 * t;
            *(float2*)(C + r0 * Ndim + c0) =
                make_float2(acc[mi][ni][0], acc[mi][ni][1]);
            *(float2*)(C + (r0 + 8) * Ndim + c0) =
                make_float2(acc[mi][ni][2], acc[mi][ni][3]);
        }
    }
}

// ---------------------------------------------------------------------------
// RoPE (in-place on q and k).
// ---------------------------------------------------------------------------
__global__ void rope_kernel(float* __restrict__ q, float* __restrict__ k,
                            const float* __restrict__ fc) {
    int idx = blockIdx.x * blockDim.x + threadIdx.x;
    if (idx >= MROWS * (DIMD / 2)) return;
    int row = idx >> 10;
    int p   = idx & 1023;
    int i   = p & 63;
    int s   = row & (SEQ - 1);
    float c  = fc[(s * 64 + i) * 2 + 0];
    float sn = fc[(s * 64 + i) * 2 + 1];
    float2* qp = (float2*)q + idx;
    float2* kp = (float2*)k + idx;
    float2 qv = *qp, kv = *kp;
    *qp = make_float2(qv.x * c - qv.y * sn, qv.x * sn + qv.y * c);
    *kp = make_float2(kv.x * c - kv.y * sn, kv.x * sn + kv.y * c);
}

// ---------------------------------------------------------------------------
// Tensor-core causal flash attention (tf32 mma.sync, fp32 softmax).
// Block: 128 Q-rows x (head, batch). 8 warps, warp = 16 rows x full width.
// K-tile 64. S via QK^T mma; P staged through smem; PV via mma.
// ---------------------------------------------------------------------------
#define QS_STRIDE 132
#define KS_STRIDE 132
#define VS_STRIDE 136
#define PS_STRIDE 68

__global__ __launch_bounds__(256) void flash_tc_kernel(const float* __restrict__ Q,
                                                       const float* __restrict__ K,
                                                       const float* __restrict__ V,
                                                       float* __restrict__ O) {
    extern __shared__ float sm[];
    float* Qs = sm;                            // [128][132]
    float* Ks = Qs + 128 * QS_STRIDE;          // [64][132]
    float* Vs = Ks + 64 * KS_STRIDE;           // [64][136]
    float* Ps = Vs + 64 * VS_STRIDE;           // [128][68]

    const int qt = (int)gridDim.x - 1 - (int)blockIdx.x;   // heavy tiles first
    const int h  = blockIdx.y;
    const int b  = blockIdx.z;
    const int tid  = threadIdx.x;
    const int wid  = tid >> 5;
    const int lane = tid & 31;
    const int g = lane >> 2;
    const int t = lane & 3;
    const int wm = wid * 16;                  // warp's row offset in Q tile
    const int q0 = qt * 128;
    const size_t base = (size_t)b * SEQ * DIMD + (size_t)h * HDD;
    const float scale = 0.08838834764831845f; // 1/sqrt(128)

    // load Q tile (tf32-rounded)
    for (int i = tid; i < 128 * 32; i += 256) {
        int r  = i >> 5;
        int d4 = (i & 31) << 2;
        float4 v = *(const float4*)(Q + base + (size_t)(q0 + r) * DIMD + d4);
        float* p = Qs + r * QS_STRIDE + d4;
        p[0] = to_tf32(v.x); p[1] = to_tf32(v.y);
        p[2] = to_tf32(v.z); p[3] = to_tf32(v.w);
    }

    float m0 = -1e30f, m1 = -1e30f, l0 = 0.f, l1 = 0.f;
    float oac[16][4];
#pragma unroll
    for (int nf = 0; nf < 16; nf++)
#pragma unroll
        for (int c = 0; c < 4; c++) oac[nf][c] = 0.f;

    __syncthreads();

    const int row0 = q0 + wm + g;     // this thread's first accum row
    const int row1 = row0 + 8;        // second accum row
    const int n_kt = 2 * (qt + 1);

    for (int kt = 0; kt < n_kt; kt++) {
        const int k0 = kt * 64;
        // fill K, V tiles (tf32-rounded)
        for (int i = tid; i < 64 * 32; i += 256) {
            int r  = i >> 5;
            int d4 = (i & 31) << 2;
            float4 kv = *(const float4*)(K + base + (size_t)(k0 + r) * DIMD + d4);
            float4 vv = *(const float4*)(V + base + (size_t)(k0 + r) * DIMD + d4);
            float* kp = Ks + r * KS_STRIDE + d4;
            kp[0] = to_tf32(kv.x); kp[1] = to_tf32(kv.y);
            kp[2] = to_tf32(kv.z); kp[3] = to_tf32(kv.w);
            float* vp = Vs + r * VS_STRIDE + d4;
            vp[0] = to_tf32(vv.x); vp[1] = to_tf32(vv.y);
            vp[2] = to_tf32(vv.z); vp[3] = to_tf32(vv.w);
        }
        __syncthreads();

        // ---- S = Q K^T : warp computes rows wm..wm+15, cols 0..63 ----
        float sacc[8][4];
#pragma unroll
        for (int nf = 0; nf < 8; nf++)
#pragma unroll
            for (int c = 0; c < 4; c++) sacc[nf][c] = 0.f;

#pragma unroll
        for (int ks = 0; ks < 16; ks++) {
            const int kk = ks * 8;
            uint32_t a0 = __float_as_uint(Qs[(wm + g) * QS_STRIDE + kk + t]);
            uint32_t a1 = __float_as_uint(Qs[(wm + g + 8) * QS_STRIDE + kk + t]);
            uint32_t a2 = __float_as_uint(Qs[(wm + g) * QS_STRIDE + kk + t + 4]);
            uint32_t a3 = __float_as_uint(Qs[(wm + g + 8) * QS_STRIDE + kk + t + 4]);
#pragma unroll
            for (int nf = 0; nf < 8; nf++) {
                uint32_t b0 = __float_as_uint(Ks[(nf * 8 + g) * KS_STRIDE + kk + t]);
                uint32_t b1 = __float_as_uint(Ks[(nf * 8 + g) * KS_STRIDE + kk + t + 4]);
                MMA_TF32(sacc[nf], a0, a1, a2, a3, b0, b1);
            }
        }

        // ---- scale + causal mask ----
        const bool need_mask = (k0 + 63 > q0 + wm);
#pragma unroll
        for (int nf = 0; nf < 8; nf++) {
            int c = k0 + nf * 8 + 2 * t;
            float s0 = sacc[nf][0] * scale;
            float s1 = sacc[nf][1] * scale;
            float s2 = sacc[nf][2] * scale;
            float s3 = sacc[nf][3] * scale;
            if (need_mask) {
                if (c     > row0) s0 = -1e30f;
                if (c + 1 > row0) s1 = -1e30f;
                if (c     > row1) s2 = -1e30f;
                if (c + 1 > row1) s3 = -1e30f;
            }
            sacc[nf][0] = s0; sacc[nf][1] = s1;
            sacc[nf][2] = s2; sacc[nf][3] = s3;
        }

        // ---- online softmax (rows warp-local; reduce over 4 t-lanes) ----
        float mx0 = -1e30f, mx1 = -1e30f;
#pragma unroll
        for (int nf = 0; nf < 8; nf++) {
            mx0 = fmaxf(mx0, fmaxf(sacc[nf][0], sacc[nf][1]));
            mx1 = fmaxf(mx1, fmaxf(sacc[nf][2], sacc[nf][3]));
        }
        mx0 = fmaxf(mx0, __shfl_xor_sync(0xffffffffu, mx0, 1));
        mx0 = fmaxf(mx0, __shfl_xor_sync(0xffffffffu, mx0, 2));
        mx1 = fmaxf(mx1, __shfl_xor_sync(0xffffffffu, mx1, 1));
        mx1 = fmaxf(mx1, __shfl_xor_sync(0xffffffffu, mx1, 2));

        float mn0 = fmaxf(m0, mx0);
        float mn1 = fmaxf(m1, mx1);
        float corr0 = __expf(m0 - mn0);
        float corr1 = __expf(m1 - mn1);
        m0 = mn0; m1 = mn1;

        float rs0 = 0.f, rs1 = 0.f;
#pragma unroll
        for (int nf = 0; nf < 8; nf++) {
            float p0 = __expf(sacc[nf][0] - mn0);
            float p1 = __expf(sacc[nf][1] - mn0);
            float p2 = __expf(sacc[nf][2] - mn1);
            float p3 = __expf(sacc[nf][3] - mn1);
            rs0 += p0 + p1;
            rs1 += p2 + p3;
            int cc = nf * 8 + 2 * t;
            *(float2*)(Ps + (wm + g) * PS_STRIDE + cc) =
                make_float2(to_tf32(p0), to_tf32(p1));
            *(float2*)(Ps + (wm + g + 8) * PS_STRIDE + cc) =
                make_float2(to_tf32(p2), to_tf32(p3));
        }
        rs0 += __shfl_xor_sync(0xffffffffu, rs0, 1);
        rs0 += __shfl_xor_sync(0xffffffffu, rs0, 2);
        rs1 += __shfl_xor_sync(0xffffffffu, rs1, 1);
        rs1 += __shfl_xor_sync(0xffffffffu, rs1, 2);
        l0 = l0 * corr0 + rs0;
        l1 = l1 * corr1 + rs1;

#pragma unroll
        for (int nf = 0; nf < 16; nf++) {
            oac[nf][0] *= corr0; oac[nf][1] *= corr0;
            oac[nf][2] *= corr1; oac[nf][3] *= corr1;
        }
        __syncwarp();   // P rows are warp-private: order store->load within warp

        // ---- O += P V : k=64 (8 k-steps), n=128 (16 n-frags) ----
#pragma unroll
        for (int ks = 0; ks < 8; ks++) {
            const int kk = ks * 8;
            uint32_t a0 = __float_as_uint(Ps[(wm + g) * PS_STRIDE + kk + t]);
            uint32_t a1 = __float_as_uint(Ps[(wm + g + 8) * PS_STRIDE + kk + t]);
            uint32_t a2 = __float_as_uint(Ps[(wm + g) * PS_STRIDE + kk + t + 4]);
            uint32_t a3 = __float_as_uint(Ps[(wm + g + 8) * PS_STRIDE + kk + t + 4]);
#pragma unroll
            for (int nf = 0; nf < 16; nf++) {
                uint32_t b0 = __float_as_uint(Vs[(kk + t) * VS_STRIDE + nf * 8 + g]);
                uint32_t b1 = __float_as_uint(Vs[(kk + t + 4) * VS_STRIDE + nf * 8 + g]);
                MMA_TF32(oac[nf], a0, a1, a2, a3, b0, b1);
            }
        }
        __syncthreads();   // protect Ks/Vs for next iteration's fill
    }

    // ---- normalize and write O ----
    float inv0 = 1.f / l0;
    float inv1 = 1.f / l1;
#pragma unroll
    for (int nf = 0; nf < 16; nf++) {
        int col = nf * 8 + 2 * t;
        *(float2*)(O + base + (size_t)row0 * DIMD + col) =
            make_float2(oac[nf][0] * inv0, oac[nf][1] * inv0);
        *(float2*)(O + base + (size_t)row1 * DIMD + col) =
            make_float2(oac[nf][2] * inv1, oac[nf][3] * inv1);
    }
}

// ---------------------------------------------------------------------------
// launcher
// ---------------------------------------------------------------------------
extern "C" void kernel_launch(void* const* d_in, const int* in_sizes, int n_in,
                              void* d_out, int out_size) {
    // metadata order: x, start_pos, freqs_cis, mask, wq, wk, wv, wo
    const float* x  = (const float*)d_in[0];
    const float* fc = (const float*)d_in[2];
    const float* wq = (const float*)d_in[4];
    const float* wk = (const float*)d_in[5];
    const float* wv = (const float*)d_in[6];
    const float* wo = (const float*)d_in[7];
    float* out = (float*)d_out;

    float *q, *k, *v, *attn;
    cudaGetSymbolAddress((void**)&q, g_q);
    cudaGetSymbolAddress((void**)&k, g_k);
    cudaGetSymbolAddress((void**)&v, g_v);
    cudaGetSymbolAddress((void**)&attn, g_attn);

    const size_t FLASH_SMEM =
        (size_t)(128 * QS_STRIDE + 64 * KS_STRIDE + 64 * VS_STRIDE +
                 128 * PS_STRIDE) * sizeof(float);
    cudaFuncSetAttribute(flash_tc_kernel,
                         cudaFuncAttributeMaxDynamicSharedMemorySize,
                         (int)FLASH_SMEM);

    dim3 ggrid(DIMD / 128, MROWS / 128);
    tf32_gemm_nt<<<ggrid, 256>>>(x, wq, q, DIMD, DIMD);
    tf32_gemm_nt<<<ggrid, 256>>>(x, wk, k, DIMD, DIMD);
    tf32_gemm_nt<<<ggrid, 256>>>(x, wv, v, DIMD, DIMD);

    rope_kernel<<<(MROWS * (DIMD / 2) + 255) / 256, 256>>>(q, k, fc);

    flash_tc_kernel<<<dim3(SEQ / 128, NHH, 2), 256, FLASH_SMEM>>>(q, k, v, attn);

    tf32_gemm_nt<<<ggrid, 256>>>(attn, wo, out, DIMD, DIMD);
}

// round 6
// speedup vs baseline: 3.6419x; 1.1067x over previous
#include <cuda_runtime.h>
#include <cstdint>

// Problem constants
#define SEQ  2048
#define DIMD 2048
#define NHH  16
#define HDD  128
#define MROWS 4096   // B * SEQ

// ---------------------------------------------------------------------------
// Scratch (device globals; no allocation allowed)
// ---------------------------------------------------------------------------
__device__ float g_q[8388608];     // [MROWS][DIMD]
__device__ float g_k[8388608];
__device__ float g_v[8388608];
__device__ float g_attn[8388608];

__device__ __forceinline__ float to_tf32(float x) {
    float y;
    asm("cvt.rna.tf32.f32 %0, %1;" : "=f"(y) : "f"(x));
    return y;
}

__device__ __forceinline__ void cp_async16(void* smem_dst, const void* gsrc) {
    uint32_t d = (uint32_t)__cvta_generic_to_shared(smem_dst);
    asm volatile("cp.async.ca.shared.global [%0], [%1], 16;\n"
                 :: "r"(d), "l"(gsrc));
}

#define MMA_TF32(acc, a0, a1, a2, a3, b0, b1)                                 \
    asm volatile(                                                             \
        "mma.sync.aligned.m16n8k8.row.col.f32.tf32.tf32.f32 "                 \
        "{%0,%1,%2,%3}, {%4,%5,%6,%7}, {%8,%9}, {%0,%1,%2,%3};"               \
        : "+f"((acc)[0]), "+f"((acc)[1]), "+f"((acc)[2]), "+f"((acc)[3])      \
        : "r"(a0), "r"(a1), "r"(a2), "r"(a3), "r"(b0), "r"(b1))

// ---------------------------------------------------------------------------
// tf32 NT GEMM via mma.sync.m16n8k8 (unchanged from R3/R4):
//   C[M,N] = A[M,K] * B[N,K]^T
// ---------------------------------------------------------------------------
__global__ __launch_bounds__(256) void tf32_gemm_nt(const float* __restrict__ A,
                                                    const float* __restrict__ B,
                                                    float* __restrict__ C,
                                                    int Kdim, int Ndim) {
    __shared__ float As[128][36];
    __shared__ float Bs[128][36];

    const int tid = threadIdx.x;
    const int bm = blockIdx.y * 128;
    const int bn = blockIdx.x * 128;
    const int wid  = tid >> 5;
    const int lane = tid & 31;
    const int wm = (wid >> 2) * 64;
    const int wn = (wid & 3) * 32;
    const int g  = lane >> 2;
    const int t  = lane & 3;

    const int row0 = tid >> 3;
    const int kq4  = (tid & 7) << 2;
    const float* Ab = A + (size_t)(bm + row0) * Kdim + kq4;
    const float* Bb = B + (size_t)(bn + row0) * Kdim + kq4;

    float acc[4][4][4];
#pragma unroll
    for (int mi = 0; mi < 4; mi++)
#pragma unroll
        for (int ni = 0; ni < 4; ni++)
#pragma unroll
            for (int c = 0; c < 4; c++) acc[mi][ni][c] = 0.f;

    float4 av[4], bv[4];
#pragma unroll
    for (int it = 0; it < 4; it++) {
        av[it] = *(const float4*)(Ab + (size_t)it * 32 * Kdim);
        bv[it] = *(const float4*)(Bb + (size_t)it * 32 * Kdim);
    }

    for (int k0 = 0; k0 < Kdim; k0 += 32) {
#pragma unroll
        for (int it = 0; it < 4; it++) {
            int r = row0 + it * 32;
            As[r][kq4 + 0] = to_tf32(av[it].x);
            As[r][kq4 + 1] = to_tf32(av[it].y);
            As[r][kq4 + 2] = to_tf32(av[it].z);
            As[r][kq4 + 3] = to_tf32(av[it].w);
            Bs[r][kq4 + 0] = to_tf32(bv[it].x);
            Bs[r][kq4 + 1] = to_tf32(bv[it].y);
            Bs[r][kq4 + 2] = to_tf32(bv[it].z);
            Bs[r][kq4 + 3] = to_tf32(bv[it].w);
        }
        __syncthreads();

        if (k0 + 32 < Kdim) {
#pragma unroll
            for (int it = 0; it < 4; it++) {
                av[it] = *(const float4*)(Ab + (size_t)it * 32 * Kdim + k0 + 32);
                bv[it] = *(const float4*)(Bb + (size_t)it * 32 * Kdim + k0 + 32);
            }
        }

#pragma unroll
        for (int ks = 0; ks < 4; ks++) {
            const int kk = ks * 8;
            uint32_t ua[4][4], ub[4][2];
#pragma unroll
            for (int mi = 0; mi < 4; mi++) {
                const int m0 = wm + mi * 16;
                ua[mi][0] = __float_as_uint(As[m0 + g][kk + t]);
                ua[mi][1] = __float_as_uint(As[m0 + g + 8][kk + t]);
                ua[mi][2] = __float_as_uint(As[m0 + g][kk + t + 4]);
                ua[mi][3] = __float_as_uint(As[m0 + g + 8][kk + t + 4]);
            }
#pragma unroll
            for (int ni = 0; ni < 4; ni++) {
                const int n0 = wn + ni * 8;
                ub[ni][0] = __float_as_uint(Bs[n0 + g][kk + t]);
                ub[ni][1] = __float_as_uint(Bs[n0 + g][kk + t + 4]);
            }
#pragma unroll
            for (int mi = 0; mi < 4; mi++)
#pragma unroll
                for (int ni = 0; ni < 4; ni++)
                    MMA_TF32(acc[mi][ni], ua[mi][0], ua[mi][1], ua[mi][2],
                             ua[mi][3], ub[ni][0], ub[ni][1]);
        }
        __syncthreads();
    }

#pragma unroll
    for (int mi = 0; mi < 4; mi++) {
#pragma unroll
        for (int ni = 0; ni < 4; ni++) {
            const size_t r0 = (size_t)(bm + wm + mi * 16 + g);
            const int   c0 = bn + wn + ni * 8 + 2 * t;
            *(float2*)(C + r0 * Ndim + c0) =
                make_float2(acc[mi][ni][0], acc[mi][ni][1]);
            *(float2*)(C + (r0 + 8) * Ndim + c0) =
                make_float2(acc[mi][ni][2], acc[mi][ni][3]);
        }
    }
}

// ---------------------------------------------------------------------------
// RoPE (in-place on q and k).
// ---------------------------------------------------------------------------
__global__ void rope_kernel(float* __restrict__ q, float* __restrict__ k,
                            const float* __restrict__ fc) {
    int idx = blockIdx.x * blockDim.x + threadIdx.x;
    if (idx >= MROWS * (DIMD / 2)) return;
    int row = idx >> 10;
    int p   = idx & 1023;
    int i   = p & 63;
    int s   = row & (SEQ - 1);
    float c  = fc[(s * 64 + i) * 2 + 0];
    float sn = fc[(s * 64 + i) * 2 + 1];
    float2* qp = (float2*)q + idx;
    float2* kp = (float2*)k + idx;
    float2 qv = *qp, kv = *kp;
    *qp = make_float2(qv.x * c - qv.y * sn, qv.x * sn + qv.y * c);
    *kp = make_float2(kv.x * c - kv.y * sn, kv.x * sn + kv.y * c);
}

// ---------------------------------------------------------------------------
// Tensor-core causal flash attention, v2.
//  - S accumulator fragments reused directly as PV A-fragments via k-index
//    permutation (V rows kk+2t / kk+2t+1) -> no P smem, no extra syncs.
//  - V double-buffered via cp.async (HW tf32 truncation on V only).
//  - K double-buffered via register prefetch + cvt.rna at STS (rounding kept
//    on the softmax-sensitive path).
//  - one __syncthreads per kt iteration.
// ---------------------------------------------------------------------------
#define FS 132   // smem row stride (== 4 mod 32): conflict-free for all frags

__global__ __launch_bounds__(256) void flash_tc_kernel(const float* __restrict__ Q,
                                                       const float* __restrict__ K,
                                                       const float* __restrict__ V,
                                                       float* __restrict__ O) {
    extern __shared__ float sm[];
    float* Qs  = sm;                    // [128][FS]
    float* Ks0 = Qs + 128 * FS;         // 2 x [64][FS]
    float* Vs0 = Ks0 + 2 * 64 * FS;     // 2 x [64][FS]

    const int qt = (int)gridDim.x - 1 - (int)blockIdx.x;   // heavy tiles first
    const int h  = blockIdx.y;
    const int b  = blockIdx.z;
    const int tid  = threadIdx.x;
    const int wid  = tid >> 5;
    const int lane = tid & 31;
    const int g = lane >> 2;
    const int t = lane & 3;
    const int wm = wid * 16;
    const int q0 = qt * 128;
    const size_t base = (size_t)b * SEQ * DIMD + (size_t)h * HDD;
    const float scale = 0.08838834764831845f; // 1/sqrt(128)

    // per-thread fill slot: 8 float4 rows per matrix
    const int fr  = tid >> 5;           // row base 0..7 (+8 per j)
    const int fd4 = (tid & 31) << 2;    // float col offset 0,4,...,124

    const int n_kt = 2 * (qt + 1);

    // ---- prologue: issue V0 cp.async, prefetch K0 into regs, fill Q ----
#pragma unroll
    for (int j = 0; j < 8; j++) {
        int r = fr + j * 8;
        cp_async16(Vs0 + r * FS + fd4, V + base + (size_t)r * DIMD + fd4);
    }
    asm volatile("cp.async.commit_group;\n");

    float4 kreg[8];
#pragma unroll
    for (int j = 0; j < 8; j++) {
        int r = fr + j * 8;
        kreg[j] = *(const float4*)(K + base + (size_t)r * DIMD + fd4);
    }

    for (int i = tid; i < 128 * 32; i += 256) {
        int r  = i >> 5;
        int d4 = (i & 31) << 2;
        float4 v = *(const float4*)(Q + base + (size_t)(q0 + r) * DIMD + d4);
        float* p = Qs + r * FS + d4;
        p[0] = to_tf32(v.x); p[1] = to_tf32(v.y);
        p[2] = to_tf32(v.z); p[3] = to_tf32(v.w);
    }

    float m0 = -1e30f, m1 = -1e30f, l0 = 0.f, l1 = 0.f;
    float oac[16][4];
#pragma unroll
    for (int nf = 0; nf < 16; nf++)
#pragma unroll
        for (int c = 0; c < 4; c++) oac[nf][c] = 0.f;

    const int row0 = q0 + wm + g;
    const int row1 = row0 + 8;

    for (int kt = 0; kt < n_kt; kt++) {
        float* Ksb = Ks0 + (kt & 1) * 64 * FS;
        float* Vsb = Vs0 + (kt & 1) * 64 * FS;

        // store prefetched K tile (tf32-rounded). Buffer last read at kt-2.
#pragma unroll
        for (int j = 0; j < 8; j++) {
            int r = fr + j * 8;
            float* p = Ksb + r * FS + fd4;
            p[0] = to_tf32(kreg[j].x); p[1] = to_tf32(kreg[j].y);
            p[2] = to_tf32(kreg[j].z); p[3] = to_tf32(kreg[j].w);
        }
        asm volatile("cp.async.wait_group 0;\n");
        __syncthreads();     // K stores + V copies visible; warps aligned

        // issue next V + prefetch next K (overlaps with compute below)
        if (kt + 1 < n_kt) {
            const int k0n = (kt + 1) * 64;
            float* Vsn = Vs0 + ((kt + 1) & 1) * 64 * FS;
#pragma unroll
            for (int j = 0; j < 8; j++) {
                int r = fr + j * 8;
                cp_async16(Vsn + r * FS + fd4,
                           V + base + (size_t)(k0n + r) * DIMD + fd4);
            }
            asm volatile("cp.async.commit_group;\n");
#pragma unroll
            for (int j = 0; j < 8; j++) {
                int r = fr + j * 8;
                kreg[j] = *(const float4*)(K + base + (size_t)(k0n + r) * DIMD + fd4);
            }
        }

        const int k0 = kt * 64;

        // ---- S = Q K^T : warp rows wm..wm+15, cols 0..63 ----
        float sacc[8][4];
#pragma unroll
        for (int nf = 0; nf < 8; nf++)
#pragma unroll
            for (int c = 0; c < 4; c++) sacc[nf][c] = 0.f;

#pragma unroll
        for (int ks = 0; ks < 16; ks++) {
            const int kk = ks * 8;
            uint32_t a0 = __float_as_uint(Qs[(wm + g) * FS + kk + t]);
            uint32_t a1 = __float_as_uint(Qs[(wm + g + 8) * FS + kk + t]);
            uint32_t a2 = __float_as_uint(Qs[(wm + g) * FS + kk + t + 4]);
            uint32_t a3 = __float_as_uint(Qs[(wm + g + 8) * FS + kk + t + 4]);
#pragma unroll
            for (int nf = 0; nf < 8; nf++) {
                uint32_t b0 = __float_as_uint(Ksb[(nf * 8 + g) * FS + kk + t]);
                uint32_t b1 = __float_as_uint(Ksb[(nf * 8 + g) * FS + kk + t + 4]);
                MMA_TF32(sacc[nf], a0, a1, a2, a3, b0, b1);
            }
        }

        // ---- scale + causal mask ----
        const bool need_mask = (k0 + 63 > q0 + wm);
#pragma unroll
        for (int nf = 0; nf < 8; nf++) {
            int c = k0 + nf * 8 + 2 * t;
            float s0 = sacc[nf][0] * scale;
            float s1 = sacc[nf][1] * scale;
            float s2 = sacc[nf][2] * scale;
            float s3 = sacc[nf][3] * scale;
            if (need_mask) {
                if (c     > row0) s0 = -1e30f;
                if (c + 1 > row0) s1 = -1e30f;
                if (c     > row1) s2 = -1e30f;
                if (c + 1 > row1) s3 = -1e30f;
            }
            sacc[nf][0] = s0; sacc[nf][1] = s1;
            sacc[nf][2] = s2; sacc[nf][3] = s3;
        }

        // ---- online softmax (reduce over 4 t-lanes) ----
        float mx0 = -1e30f, mx1 = -1e30f;
#pragma unroll
        for (int nf = 0; nf < 8; nf++) {
            mx0 = fmaxf(mx0, fmaxf(sacc[nf][0], sacc[nf][1]));
            mx1 = fmaxf(mx1, fmaxf(sacc[nf][2], sacc[nf][3]));
        }
        mx0 = fmaxf(mx0, __shfl_xor_sync(0xffffffffu, mx0, 1));
        mx0 = fmaxf(mx0, __shfl_xor_sync(0xffffffffu, mx0, 2));
        mx1 = fmaxf(mx1, __shfl_xor_sync(0xffffffffu, mx1, 1));
        mx1 = fmaxf(mx1, __shfl_xor_sync(0xffffffffu, mx1, 2));

        float mn0 = fmaxf(m0, mx0);
        float mn1 = fmaxf(m1, mx1);
        float corr0 = __expf(m0 - mn0);
        float corr1 = __expf(m1 - mn1);
        m0 = mn0; m1 = mn1;

        float rs0 = 0.f, rs1 = 0.f;
        // exp + pack P directly as PV A-fragments:
        //  contraction position t -> col 2t, t+4 -> col 2t+1
        //  => a0 = P(g,2t)=p0, a1 = P(g+8,2t)=p2, a2 = P(g,2t+1)=p1, a3 = p3
#pragma unroll
        for (int nf = 0; nf < 8; nf++) {
            float p0 = __expf(sacc[nf][0] - mn0);
            float p1 = __expf(sacc[nf][1] - mn0);
            float p2 = __expf(sacc[nf][2] - mn1);
            float p3 = __expf(sacc[nf][3] - mn1);
            rs0 += p0 + p1;
            rs1 += p2 + p3;
            sacc[nf][0] = to_tf32(p0);
            sacc[nf][1] = to_tf32(p2);
            sacc[nf][2] = to_tf32(p1);
            sacc[nf][3] = to_tf32(p3);
        }
        rs0 += __shfl_xor_sync(0xffffffffu, rs0, 1);
        rs0 += __shfl_xor_sync(0xffffffffu, rs0, 2);
        rs1 += __shfl_xor_sync(0xffffffffu, rs1, 1);
        rs1 += __shfl_xor_sync(0xffffffffu, rs1, 2);
        l0 = l0 * corr0 + rs0;
        l1 = l1 * corr1 + rs1;

#pragma unroll
        for (int nf = 0; nf < 16; nf++) {
            oac[nf][0] *= corr0; oac[nf][1] *= corr0;
            oac[nf][2] *= corr1; oac[nf][3] *= corr1;
        }

        // ---- O += P V  (B rows permuted to match: kk+2t, kk+2t+1) ----
#pragma unroll
        for (int ks = 0; ks < 8; ks++) {
            const int kk = ks * 8;
            uint32_t a0 = __float_as_uint(sacc[ks][0]);
            uint32_t a1 = __float_as_uint(sacc[ks][1]);
            uint32_t a2 = __float_as_uint(sacc[ks][2]);
            uint32_t a3 = __float_as_uint(sacc[ks][3]);
#pragma unroll
            for (int nf = 0; nf < 16; nf++) {
                uint32_t b0 = __float_as_uint(Vsb[(kk + 2 * t) * FS + nf * 8 + g]);
                uint32_t b1 = __float_as_uint(Vsb[(kk + 2 * t + 1) * FS + nf * 8 + g]);
                MMA_TF32(oac[nf], a0, a1, a2, a3, b0, b1);
            }
        }
        // no trailing sync: next iter writes only the other buffer; the
        // conflict (buf kt&1) is two iterations away, behind the next sync.
    }

    // ---- normalize and write O ----
    float inv0 = 1.f / l0;
    float inv1 = 1.f / l1;
#pragma unroll
    for (int nf = 0; nf < 16; nf++) {
        int col = nf * 8 + 2 * t;
        *(float2*)(O + base + (size_t)row0 * DIMD + col) =
            make_float2(oac[nf][0] * inv0, oac[nf][1] * inv0);
        *(float2*)(O + base + (size_t)row1 * DIMD + col) =
            make_float2(oac[nf][2] * inv1, oac[nf][3] * inv1);
    }
}

// ---------------------------------------------------------------------------
// launcher
// ---------------------------------------------------------------------------
extern "C" void kernel_launch(void* const* d_in, const int* in_sizes, int n_in,
                              void* d_out, int out_size) {
    // metadata order: x, start_pos, freqs_cis, mask, wq, wk, wv, wo
    const float* x  = (const float*)d_in[0];
    const float* fc = (const float*)d_in[2];
    const float* wq = (const float*)d_in[4];
    const float* wk = (const float*)d_in[5];
    const float* wv = (const float*)d_in[6];
    const float* wo = (const float*)d_in[7];
    float* out = (float*)d_out;

    float *q, *k, *v, *attn;
    cudaGetSymbolAddress((void**)&q, g_q);
    cudaGetSymbolAddress((void**)&k, g_k);
    cudaGetSymbolAddress((void**)&v, g_v);
    cudaGetSymbolAddress((void**)&attn, g_attn);

    const size_t FLASH_SMEM = (size_t)(128 + 4 * 64) * FS * sizeof(float); // 198KB
    cudaFuncSetAttribute(flash_tc_kernel,
                         cudaFuncAttributeMaxDynamicSharedMemorySize,
                         (int)FLASH_SMEM);

    dim3 ggrid(DIMD / 128, MROWS / 128);
    tf32_gemm_nt<<<ggrid, 256>>>(x, wq, q, DIMD, DIMD);
    tf32_gemm_nt<<<ggrid, 256>>>(x, wk, k, DIMD, DIMD);
    tf32_gemm_nt<<<ggrid, 256>>>(x, wv, v, DIMD, DIMD);

    rope_kernel<<<(MROWS * (DIMD / 2) + 255) / 256, 256>>>(q, k, fc);

    flash_tc_kernel<<<dim3(SEQ / 128, NHH, 2), 256, FLASH_SMEM>>>(q, k, v, attn);

    tf32_gemm_nt<<<ggrid, 256>>>(attn, wo, out, DIMD, DIMD);
}

// round 9
// speedup vs baseline: 5.9523x; 1.6344x over previous
#include <cuda_runtime.h>
#include <cuda_fp16.h>
#include <cstdint>

// Problem constants
#define SEQ  2048
#define DIMD 2048
#define NHH  16
#define HDD  128
#define MROWS 4096   // B * SEQ

// ---------------------------------------------------------------------------
// Scratch (device globals; no allocation allowed)
// ---------------------------------------------------------------------------
__device__ float  g_q[8388608];     // [MROWS][DIMD] f32
__device__ float  g_k[8388608];
__device__ float  g_v[8388608];
__device__ float  g_attn[8388608];
__device__ __half g_qh[8388608];    // rope'd Q, half
__device__ __half g_kh[8388608];    // rope'd K, half
__device__ __half g_vt[8388608];    // V transposed: [B][NH][HD][SEQ], half

__device__ __forceinline__ void cp_async16(void* smem_dst, const void* gsrc) {
    uint32_t d = (uint32_t)__cvta_generic_to_shared(smem_dst);
    asm volatile("cp.async.ca.shared.global [%0], [%1], 16;\n"
                 :: "r"(d), "l"(gsrc));
}

__device__ __forceinline__ uint32_t packh2(float a, float b) {
    __half2 h = __floats2half2_rn(a, b);
    return *reinterpret_cast<uint32_t*>(&h);
}

#define MMA_F16(acc, a0, a1, a2, a3, b0, b1)                                  \
    asm volatile(                                                             \
        "mma.sync.aligned.m16n8k16.row.col.f32.f16.f16.f32 "                  \
        "{%0,%1,%2,%3}, {%4,%5,%6,%7}, {%8,%9}, {%0,%1,%2,%3};"               \
        : "+f"((acc)[0]), "+f"((acc)[1]), "+f"((acc)[2]), "+f"((acc)[3])      \
        : "r"(a0), "r"(a1), "r"(a2), "r"(a3), "r"(b0), "r"(b1))

// ---------------------------------------------------------------------------
// fp16 NT GEMM via mma.sync.m16n8k16 (f32 I/O, f32 accumulate):
//   C[M,N] = A[M,K] * B[N,K]^T
// 128x128x32 tile, 8 warps (2x4), warp 64x32. smem half [128][40] per matrix.
// ---------------------------------------------------------------------------
__global__ __launch_bounds__(256) void h16_gemm_nt(const float* __restrict__ A,
                                                   const float* __restrict__ B,
                                                   float* __restrict__ C,
                                                   int Kdim, int Ndim) {
    __shared__ __half As[128][40];
    __shared__ __half Bs[128][40];

    const int tid = threadIdx.x;
    const int bm = blockIdx.y * 128;
    const int bn = blockIdx.x * 128;
    const int wid  = tid >> 5;
    const int lane = tid & 31;
    const int wm = (wid >> 2) * 64;
    const int wn = (wid & 3) * 32;
    const int g  = lane >> 2;
    const int t  = lane & 3;

    const int row0 = tid >> 3;
    const int kq4  = (tid & 7) << 2;    // f32 col offset 0..28
    const float* Ab = A + (size_t)(bm + row0) * Kdim + kq4;
    const float* Bb = B + (size_t)(bn + row0) * Kdim + kq4;

    float acc[4][4][4];
#pragma unroll
    for (int mi = 0; mi < 4; mi++)
#pragma unroll
        for (int ni = 0; ni < 4; ni++)
#pragma unroll
            for (int c = 0; c < 4; c++) acc[mi][ni][c] = 0.f;

    float4 av[4], bv[4];
#pragma unroll
    for (int it = 0; it < 4; it++) {
        av[it] = *(const float4*)(Ab + (size_t)it * 32 * Kdim);
        bv[it] = *(const float4*)(Bb + (size_t)it * 32 * Kdim);
    }

    for (int k0 = 0; k0 < Kdim; k0 += 32) {
#pragma unroll
        for (int it = 0; it < 4; it++) {
            int r = row0 + it * 32;
            uint2 ah, bh;
            ah.x = packh2(av[it].x, av[it].y);
            ah.y = packh2(av[it].z, av[it].w);
            bh.x = packh2(bv[it].x, bv[it].y);
            bh.y = packh2(bv[it].z, bv[it].w);
            *(uint2*)(&As[r][kq4]) = ah;
            *(uint2*)(&Bs[r][kq4]) = bh;
        }
        __syncthreads();

        if (k0 + 32 < Kdim) {
#pragma unroll
            for (int it = 0; it < 4; it++) {
                av[it] = *(const float4*)(Ab + (size_t)it * 32 * Kdim + k0 + 32);
                bv[it] = *(const float4*)(Bb + (size_t)it * 32 * Kdim + k0 + 32);
            }
        }

#pragma unroll
        for (int ks = 0; ks < 2; ks++) {
            const int kk = ks * 16;
            uint32_t ua[4][4], ub[4][2];
#pragma unroll
            for (int mi = 0; mi < 4; mi++) {
                const int m0 = wm + mi * 16;
                ua[mi][0] = *(const uint32_t*)(&As[m0 + g][kk + 2 * t]);
                ua[mi][1] = *(const uint32_t*)(&As[m0 + g + 8][kk + 2 * t]);
                ua[mi][2] = *(const uint32_t*)(&As[m0 + g][kk + 2 * t + 8]);
                ua[mi][3] = *(const uint32_t*)(&As[m0 + g + 8][kk + 2 * t + 8]);
            }
#pragma unroll
            for (int ni = 0; ni < 4; ni++) {
                const int n0 = wn + ni * 8;
                ub[ni][0] = *(const uint32_t*)(&Bs[n0 + g][kk + 2 * t]);
                ub[ni][1] = *(const uint32_t*)(&Bs[n0 + g][kk + 2 * t + 8]);
            }
#pragma unroll
            for (int mi = 0; mi < 4; mi++)
#pragma unroll
                for (int ni = 0; ni < 4; ni++)
                    MMA_F16(acc[mi][ni], ua[mi][0], ua[mi][1], ua[mi][2],
                            ua[mi][3], ub[ni][0], ub[ni][1]);
        }
        __syncthreads();
    }

#pragma unroll
    for (int mi = 0; mi < 4; mi++) {
#pragma unroll
        for (int ni = 0; ni < 4; ni++) {
            const size_t r0 = (size_t)(bm + wm + mi * 16 + g);
            const int   c0 = bn + wn + ni * 8 + 2 * t;
            *(float2*)(C + r0 * Ndim + c0) =
                make_float2(acc[mi][ni][0], acc[mi][ni][1]);
            *(float2*)(C + (r0 + 8) * Ndim + c0) =
                make_float2(acc[mi][ni][2], acc[mi][ni][3]);
        }
    }
}

// ---------------------------------------------------------------------------
// RoPE: read f32 q/k, apply rotation, write HALF q/k.
// ---------------------------------------------------------------------------
__global__ void rope_half_kernel(const float* __restrict__ q,
                                 const float* __restrict__ k,
                                 const float* __restrict__ fc,
                                 __half* __restrict__ qh,
                                 __half* __restrict__ kh) {
    int idx = blockIdx.x * blockDim.x + threadIdx.x;   // pair index
    if (idx >= MROWS * (DIMD / 2)) return;
    int row = idx >> 10;
    int p   = idx & 1023;
    int i   = p & 63;
    int s   = row & (SEQ - 1);
    float c  = fc[(s * 64 + i) * 2 + 0];
    float sn = fc[(s * 64 + i) * 2 + 1];
    float2 qv = ((const float2*)q)[idx];
    float2 kv = ((const float2*)k)[idx];
    ((__half2*)qh)[idx] = __floats2half2_rn(qv.x * c - qv.y * sn,
                                            qv.x * sn + qv.y * c);
    ((__half2*)kh)[idx] = __floats2half2_rn(kv.x * c - kv.y * sn,
                                            kv.x * sn + kv.y * c);
}

// ---------------------------------------------------------------------------
// V transpose: v f32 [B*SEQ][DIMD] -> vt half [B][NH][HD][SEQ]
// ---------------------------------------------------------------------------
__global__ void transpose_v_kernel(const float* __restrict__ v,
                                   __half* __restrict__ vt) {
    __shared__ float tile[32][33];
    const int s0 = blockIdx.x * 32;
    const int c0 = blockIdx.y * 32;
    const int b  = blockIdx.z;
    const int x = threadIdx.x, y = threadIdx.y;   // 32 x 8
#pragma unroll
    for (int j = 0; j < 4; j++) {
        int s = s0 + y * 4 + j;
        tile[y * 4 + j][x] = v[(size_t)(b * SEQ + s) * DIMD + c0 + x];
    }
    __syncthreads();
#pragma unroll
    for (int j = 0; j < 4; j++) {
        int c = c0 + y * 4 + j;
        int h = c >> 7, d = c & 127;
        vt[((size_t)(b * NHH + h) * HDD + d) * SEQ + s0 + x] =
            __float2half_rn(tile[x][y * 4 + j]);
    }
}

// ---------------------------------------------------------------------------
// fp16 tensor-core causal flash attention, persistent serpentine grid.
// 296 CTAs x 256 thr; tile = 128 q-rows x (head,batch); K-tile 64.
// All tiles cp.async'd as half; every fragment load is a half2 LDS.32.
// S accum -> PV A-frags by identity mapping (fp16 k16 layout).
// ---------------------------------------------------------------------------
#define QSH 136   // Q/K smem stride in halves (68 words == 4 mod 32)
#define VSH 72    // Vt smem stride in halves (36 words == 4 mod 32)
#define NTILES 512
#define NCTAS 296

__global__ __launch_bounds__(256, 2) void flash_fp16_kernel(
        const __half* __restrict__ Qh, const __half* __restrict__ Kh,
        const __half* __restrict__ Vt, float* __restrict__ O) {
    extern __shared__ __half smh[];
    __half* Qs  = smh;                    // [128][QSH]
    __half* Ks0 = Qs + 128 * QSH;         // 2 x [64][QSH]
    __half* Vs0 = Ks0 + 2 * 64 * QSH;     // 2 x [128][VSH]

    const int cta  = blockIdx.x;
    const int tid  = threadIdx.x;
    const int wid  = tid >> 5;
    const int lane = tid & 31;
    const int g = lane >> 2;
    const int t = lane & 3;
    const int wm = wid * 16;
    const float scale = 0.08838834764831845f;   // 1/sqrt(128)

    for (int rnd = 0; rnd < 2; rnd++) {
        int tile;
        if (rnd == 0) tile = cta;
        else {
            tile = 2 * NCTAS - 1 - cta;               // 591 - cta
            if (tile >= NTILES || tile < NCTAS) break;
        }
        // tiles sorted heavy-first: qt = 15 - tile/32
        const int qt = 15 - (tile >> 5);
        const int hb = tile & 31;
        const int h  = hb & 15;
        const int b  = hb >> 4;
        const int q0 = qt * 128;
        const int n_kt = 2 * (qt + 1);

        const size_t qbase  = (size_t)(b * SEQ + q0) * DIMD + h * HDD;
        const size_t kbase  = (size_t)(b * SEQ) * DIMD + h * HDD;
        const size_t vtbase = (size_t)((b * NHH + h) * HDD) * SEQ;

        // ---- prologue: Q tile + K0 + V0 via cp.async ----
#pragma unroll
        for (int j = 0; j < 8; j++) {
            int cq = tid + j * 256;
            int r = cq >> 4, ch = (cq & 15) * 8;
            cp_async16(Qs + r * QSH + ch, Qh + qbase + (size_t)r * DIMD + ch);
        }
#pragma unroll
        for (int j = 0; j < 4; j++) {
            int ck = tid + j * 256;
            int r = ck >> 4, ch = (ck & 15) * 8;
            cp_async16(Ks0 + r * QSH + ch, Kh + kbase + (size_t)r * DIMD + ch);
        }
#pragma unroll
        for (int j = 0; j < 4; j++) {
            int cv = tid + j * 256;
            int r = cv >> 3, ch = (cv & 7) * 8;
            cp_async16(Vs0 + r * VSH + ch, Vt + vtbase + (size_t)r * SEQ + ch);
        }
        asm volatile("cp.async.commit_group;\n");

        float m0 = -1e30f, m1 = -1e30f, l0 = 0.f, l1 = 0.f;
        float oac[16][4];
#pragma unroll
        for (int nf = 0; nf < 16; nf++)
#pragma unroll
            for (int c = 0; c < 4; c++) oac[nf][c] = 0.f;

        const int row0 = q0 + wm + g;
        const int row1 = row0 + 8;

        for (int kt = 0; kt < n_kt; kt++) {
            __half* Ksb = Ks0 + (kt & 1) * 64 * QSH;
            __half* Vsb = Vs0 + (kt & 1) * 128 * VSH;

            asm volatile("cp.async.wait_group 0;\n");
            __syncthreads();

            // issue next K/V (into the other buffer) while computing
            if (kt + 1 < n_kt) {
                const int k0n = (kt + 1) * 64;
                __half* Ksn = Ks0 + ((kt + 1) & 1) * 64 * QSH;
                __half* Vsn = Vs0 + ((kt + 1) & 1) * 128 * VSH;
#pragma unroll
                for (int j = 0; j < 4; j++) {
                    int ck = tid + j * 256;
                    int r = ck >> 4, ch = (ck & 15) * 8;
                    cp_async16(Ksn + r * QSH + ch,
                               Kh + kbase + (size_t)(k0n + r) * DIMD + ch);
                }
#pragma unroll
                for (int j = 0; j < 4; j++) {
                    int cv = tid + j * 256;
                    int r = cv >> 3, ch = (cv & 7) * 8;
                    cp_async16(Vsn + r * VSH + ch,
                               Vt + vtbase + (size_t)r * SEQ + k0n + ch);
                }
                asm volatile("cp.async.commit_group;\n");
            }

            const int k0 = kt * 64;

            // ---- S = Q K^T : 8 k16-steps x 8 n-frags ----
            float sacc[8][4];
#pragma unroll
            for (int nf = 0; nf < 8; nf++)
#pragma unroll
                for (int c = 0; c < 4; c++) sacc[nf][c] = 0.f;

#pragma unroll
            for (int ks = 0; ks < 8; ks++) {
                const int kk = ks * 16;
                uint32_t a0 = *(const uint32_t*)(Qs + (wm + g) * QSH + kk + 2 * t);
                uint32_t a1 = *(const uint32_t*)(Qs + (wm + g + 8) * QSH + kk + 2 * t);
                uint32_t a2 = *(const uint32_t*)(Qs + (wm + g) * QSH + kk + 2 * t + 8);
                uint32_t a3 = *(const uint32_t*)(Qs + (wm + g + 8) * QSH + kk + 2 * t + 8);
#pragma unroll
                for (int nf = 0; nf < 8; nf++) {
                    uint32_t b0 = *(const uint32_t*)(Ksb + (nf * 8 + g) * QSH + kk + 2 * t);
                    uint32_t b1 = *(const uint32_t*)(Ksb + (nf * 8 + g) * QSH + kk + 2 * t + 8);
                    MMA_F16(sacc[nf], a0, a1, a2, a3, b0, b1);
                }
            }

            // ---- scale + causal mask ----
            const bool need_mask = (k0 + 63 > q0 + wm);
#pragma unroll
            for (int nf = 0; nf < 8; nf++) {
                int c = k0 + nf * 8 + 2 * t;
                float s0 = sacc[nf][0] * scale;
                float s1 = sacc[nf][1] * scale;
                float s2 = sacc[nf][2] * scale;
                float s3 = sacc[nf][3] * scale;
                if (need_mask) {
                    if (c     > row0) s0 = -1e30f;
                    if (c + 1 > row0) s1 = -1e30f;
                    if (c     > row1) s2 = -1e30f;
                    if (c + 1 > row1) s3 = -1e30f;
                }
                sacc[nf][0] = s0; sacc[nf][1] = s1;
                sacc[nf][2] = s2; sacc[nf][3] = s3;
            }

            // ---- online softmax (reduce over the 4 t-lanes) ----
            float mx0 = -1e30f, mx1 = -1e30f;
#pragma unroll
            for (int nf = 0; nf < 8; nf++) {
                mx0 = fmaxf(mx0, fmaxf(sacc[nf][0], sacc[nf][1]));
                mx1 = fmaxf(mx1, fmaxf(sacc[nf][2], sacc[nf][3]));
            }
            mx0 = fmaxf(mx0, __shfl_xor_sync(0xffffffffu, mx0, 1));
            mx0 = fmaxf(mx0, __shfl_xor_sync(0xffffffffu, mx0, 2));
            mx1 = fmaxf(mx1, __shfl_xor_sync(0xffffffffu, mx1, 1));
            mx1 = fmaxf(mx1, __shfl_xor_sync(0xffffffffu, mx1, 2));

            float mn0 = fmaxf(m0, mx0);
            float mn1 = fmaxf(m1, mx1);
            float corr0 = __expf(m0 - mn0);
            float corr1 = __expf(m1 - mn1);
            m0 = mn0; m1 = mn1;

            float rs0 = 0.f, rs1 = 0.f;
            uint32_t pk0[8], pk1[8];
#pragma unroll
            for (int nf = 0; nf < 8; nf++) {
                float p0 = __expf(sacc[nf][0] - mn0);
                float p1 = __expf(sacc[nf][1] - mn0);
                float p2 = __expf(sacc[nf][2] - mn1);
                float p3 = __expf(sacc[nf][3] - mn1);
                rs0 += p0 + p1;
                rs1 += p2 + p3;
                pk0[nf] = packh2(p0, p1);     // rows g   : P[g][8nf+2t, +2t+1]
                pk1[nf] = packh2(p2, p3);     // rows g+8
            }
            rs0 += __shfl_xor_sync(0xffffffffu, rs0, 1);
            rs0 += __shfl_xor_sync(0xffffffffu, rs0, 2);
            rs1 += __shfl_xor_sync(0xffffffffu, rs1, 1);
            rs1 += __shfl_xor_sync(0xffffffffu, rs1, 2);
            l0 = l0 * corr0 + rs0;
            l1 = l1 * corr1 + rs1;

#pragma unroll
            for (int nf = 0; nf < 16; nf++) {
                oac[nf][0] *= corr0; oac[nf][1] *= corr0;
                oac[nf][2] *= corr1; oac[nf][3] *= corr1;
            }

            // ---- O += P V : 4 k16-steps, A-frags from pk (identity map) ----
#pragma unroll
            for (int ks2 = 0; ks2 < 4; ks2++) {
                uint32_t a0 = pk0[2 * ks2];
                uint32_t a1 = pk1[2 * ks2];
                uint32_t a2 = pk0[2 * ks2 + 1];
                uint32_t a3 = pk1[2 * ks2 + 1];
                const int kk = ks2 * 16;
#pragma unroll
                for (int nf = 0; nf < 16; nf++) {
                    uint32_t b0 = *(const uint32_t*)(Vsb + (nf * 8 + g) * VSH + kk + 2 * t);
                    uint32_t b1 = *(const uint32_t*)(Vsb + (nf * 8 + g) * VSH + kk + 2 * t + 8);
                    MMA_F16(oac[nf], a0, a1, a2, a3, b0, b1);
                }
            }
            // next iteration's fills target the other buffer; safe (see sync)
        }

        // ---- normalize and write O (f32) ----
        float inv0 = 1.f / l0;
        float inv1 = 1.f / l1;
        const size_t obase = (size_t)(b * SEQ) * DIMD + h * HDD;
#pragma unroll
        for (int nf = 0; nf < 16; nf++) {
            int col = nf * 8 + 2 * t;
            *(float2*)(O + obase + (size_t)row0 * DIMD + col) =
                make_float2(oac[nf][0] * inv0, oac[nf][1] * inv0);
            *(float2*)(O + obase + (size_t)row1 * DIMD + col) =
                make_float2(oac[nf][2] * inv1, oac[nf][3] * inv1);
        }
        __syncthreads();   // protect Q/K/V smem before next tile's prologue
    }
}

// ---------------------------------------------------------------------------
// launcher
// ---------------------------------------------------------------------------
extern "C" void kernel_launch(void* const* d_in, const int* in_sizes, int n_in,
                              void* d_out, int out_size) {
    // metadata order: x, start_pos, freqs_cis, mask, wq, wk, wv, wo
    const float* x  = (const float*)d_in[0];
    const float* fc = (const float*)d_in[2];
    const float* wq = (const float*)d_in[4];
    const float* wk = (const float*)d_in[5];
    const float* wv = (const float*)d_in[6];
    const float* wo = (const float*)d_in[7];
    float* out = (float*)d_out;

    float *q, *k, *v, *attn;
    __half *qh, *kh, *vt;
    cudaGetSymbolAddress((void**)&q, g_q);
    cudaGetSymbolAddress((void**)&k, g_k);
    cudaGetSymbolAddress((void**)&v, g_v);
    cudaGetSymbolAddress((void**)&attn, g_attn);
    cudaGetSymbolAddress((void**)&qh, g_qh);
    cudaGetSymbolAddress((void**)&kh, g_kh);
    cudaGetSymbolAddress((void**)&vt, g_vt);

    const size_t FLASH_SMEM =
        (size_t)(128 * QSH + 2 * 64 * QSH + 2 * 128 * VSH) * sizeof(__half);
    cudaFuncSetAttribute(flash_fp16_kernel,
                         cudaFuncAttributeMaxDynamicSharedMemorySize,
                         (int)FLASH_SMEM);

    dim3 ggrid(DIMD / 128, MROWS / 128);
    h16_gemm_nt<<<ggrid, 256>>>(x, wq, q, DIMD, DIMD);
    h16_gemm_nt<<<ggrid, 256>>>(x, wk, k, DIMD, DIMD);
    h16_gemm_nt<<<ggrid, 256>>>(x, wv, v, DIMD, DIMD);

    rope_half_kernel<<<(MROWS * (DIMD / 2) + 255) / 256, 256>>>(q, k, fc, qh, kh);
    transpose_v_kernel<<<dim3(SEQ / 32, DIMD / 32, 2), dim3(32, 8)>>>(v, vt);

    flash_fp16_kernel<<<NCTAS, 256, FLASH_SMEM>>>(qh, kh, vt, attn);

    h16_gemm_nt<<<ggrid, 256>>>(attn, wo, out, DIMD, DIMD);
}